// round 7
// baseline (speedup 1.0000x reference)
#include <cuda_runtime.h>
#include <cuda_bf16.h>
#include <cstddef>

// Problem constants
#define BSZ  64
#define TT   512
#define DD   1024
#define HH   1024
#define H4   4096
#define BT   (BSZ*TT)          // 32768
#define NBLK 128               // persistent grid size
#define KC   64                // k-chunk for h staging
#define NCHUNK (HH/KC)         // 16

// Scratch (device globals — allocation-free per harness rules)
__device__ float g_xz[(size_t)BT * H4];     // per-layer input-GEMM result (reused)
__device__ float g_out0[(size_t)BT * HH];   // layer-0 hidden outputs (B,T,H)
__device__ float g_h0[BSZ * HH];
__device__ float g_h1[BSZ * HH];

// grid-barrier state
__device__ unsigned g_bar_count = 0;
__device__ volatile unsigned g_bar_gen = 0;

__device__ __forceinline__ void grid_barrier()
{
    __syncthreads();
    if (threadIdx.x == 0) {
        __threadfence();                       // publish this block's stores
        unsigned gen = g_bar_gen;              // read BEFORE arriving
        if (atomicAdd(&g_bar_count, 1u) == NBLK - 1) {
            atomicExch(&g_bar_count, 0u);
            __threadfence();
            g_bar_gen = gen + 1;               // release
        } else {
            while (g_bar_gen == gen) { }       // volatile spin
        }
    }
    __syncthreads();
}

// ---- packed f32x2 helpers (sm_103a) -------------------------------------
__device__ __forceinline__ unsigned long long splat2(float v) {
    unsigned long long r;
    unsigned u = __float_as_uint(v);
    asm("mov.b64 %0, {%1, %1};" : "=l"(r) : "r"(u));
    return r;
}
__device__ __forceinline__ unsigned long long pack2(float x, float y) {
    unsigned long long r;
    asm("mov.b64 %0, {%1, %2};" : "=l"(r) : "r"(__float_as_uint(x)), "r"(__float_as_uint(y)));
    return r;
}
__device__ __forceinline__ void unpack2(unsigned long long p, float& x, float& y) {
    unsigned lo, hi;
    asm("mov.b64 {%0, %1}, %2;" : "=r"(lo), "=r"(hi) : "l"(p));
    x = __uint_as_float(lo);
    y = __uint_as_float(hi);
}
__device__ __forceinline__ void ffma2(unsigned long long& d, unsigned long long a,
                                      unsigned long long b) {
    asm("fma.rn.f32x2 %0, %1, %2, %0;" : "+l"(d) : "l"(a), "l"(b));
}

// ---------------------------------------------------------------------------
// Classic 128x128x8 SGEMM with bias: C[M,4096] = A[M,K] @ B[K,4096] + bias
// ---------------------------------------------------------------------------
__global__ __launch_bounds__(256) void sgemm_bias(
    const float* __restrict__ A, const float* __restrict__ Bm,
    const float* __restrict__ bias, float* __restrict__ C, int K)
{
    const int N = H4;
    __shared__ float As[8][128];
    __shared__ float Bs[8][128];

    const int tid = threadIdx.x;
    const int tx = tid & 15;
    const int ty = tid >> 4;

    const float* Ab = A + (size_t)blockIdx.y * 128 * K;
    const float* Bb = Bm + blockIdx.x * 128;

    const int arow = tid >> 1;
    const int ak   = (tid & 1) * 4;
    const int bk   = tid >> 5;
    const int bcol = (tid & 31) * 4;

    float acc[8][8];
#pragma unroll
    for (int i = 0; i < 8; i++)
#pragma unroll
        for (int j = 0; j < 8; j++) acc[i][j] = 0.f;

    for (int k0 = 0; k0 < K; k0 += 8) {
        float4 av = *(const float4*)(Ab + (size_t)arow * K + k0 + ak);
        As[ak + 0][arow] = av.x;
        As[ak + 1][arow] = av.y;
        As[ak + 2][arow] = av.z;
        As[ak + 3][arow] = av.w;
        float4 bv = *(const float4*)(Bb + (size_t)(k0 + bk) * N + bcol);
        *(float4*)&Bs[bk][bcol] = bv;
        __syncthreads();
#pragma unroll
        for (int kk = 0; kk < 8; kk++) {
            float a[8], b[8];
            *(float4*)(a)     = *(float4*)&As[kk][ty * 8];
            *(float4*)(a + 4) = *(float4*)&As[kk][ty * 8 + 4];
            *(float4*)(b)     = *(float4*)&Bs[kk][tx * 8];
            *(float4*)(b + 4) = *(float4*)&Bs[kk][tx * 8 + 4];
#pragma unroll
            for (int i = 0; i < 8; i++)
#pragma unroll
                for (int j = 0; j < 8; j++)
                    acc[i][j] = fmaf(a[i], b[j], acc[i][j]);
        }
        __syncthreads();
    }

    const int crow0 = blockIdx.y * 128 + ty * 8;
    const int ccol0 = blockIdx.x * 128 + tx * 8;
#pragma unroll
    for (int i = 0; i < 8; i++) {
        float* crow = C + (size_t)(crow0 + i) * N + ccol0;
#pragma unroll
        for (int j = 0; j < 8; j += 4) {
            float4 v;
            v.x = acc[i][j + 0] + bias[ccol0 + j + 0];
            v.y = acc[i][j + 1] + bias[ccol0 + j + 1];
            v.z = acc[i][j + 2] + bias[ccol0 + j + 2];
            v.w = acc[i][j + 3] + bias[ccol0 + j + 3];
            *(float4*)(crow + j) = v;
        }
    }
}

// ---------------------------------------------------------------------------
// Persistent LSTM layer with SMEM-resident U and packed f32x2 FMAs.
// grid = 128 blocks x 128 threads. Block: all 64 rows x 8 h-cols x 4 gates.
// U slice (1024 x 32 z-cols) loaded to smem ONCE. h staged per 64-k chunk.
// Thread: 4 rows x 1 h-col x 4 gates; acc as row-pair packed f32x2.
// ---------------------------------------------------------------------------
__global__ __launch_bounds__(128, 1) void lstm_layer(
    const float* __restrict__ xz, const float* __restrict__ U,
    const int* __restrict__ lengths,
    float* __restrict__ hb0, float* __restrict__ hb1,
    float* __restrict__ out, float* __restrict__ finalHC)
{
    extern __shared__ float sm[];
    float* us = sm;                 // [1024][32]  (128 KB) : [k][col*4 + gate]
    float* hs = sm + HH * 32;       // [KC][64]    (16 KB)  : [k][row]

    const int tid  = threadIdx.x;
    const int cg   = tid & 7;               // h-col within block (0..7)
    const int rg4  = (tid >> 3) * 4;        // first of 4 owned rows (0..60)
    const int col0 = blockIdx.x * 8;
    const int col  = col0 + cg;

    // ---- one-time: load U slice into smem ----
    // us[k][c*4+g] = U[k][g*1024 + col0 + c]
    for (int i = tid; i < HH * 32; i += 128) {
        const int k = i >> 5;
        const int s = i & 31;
        const int c = s >> 2;
        const int g = s & 3;
        us[k * 32 + c * 4 + g] = U[(size_t)k * H4 + g * HH + col0 + c];
    }

    // ---- persistent per-thread state ----
    float creg[4], hreg[4];
    int   lenr[4];
#pragma unroll
    for (int r = 0; r < 4; r++) {
        creg[r] = 0.f;
        hreg[r] = 0.f;
        lenr[r] = lengths[rg4 + r];
        hb0[(rg4 + r) * HH + col] = 0.f;   // zero-init shared h buffer
    }
    // staging role: thread stages row srow, k-half skh (32 k-values)
    const int srow = tid & 63;
    const int skh  = (tid >> 6) * 32;

    grid_barrier();   // U smem ready (block-local but syncthreads inside), h0 zeroed

    for (int t = 0; t < TT; t++) {
        const float* hprev = (t & 1) ? hb1 : hb0;
        float*       hnext = (t & 1) ? hb0 : hb1;

        // prefetch xz for this step (used only in epilogue; loads stay in flight)
        float xzv[4][4];
#pragma unroll
        for (int r = 0; r < 4; r++) {
            const size_t base = ((size_t)(rg4 + r) * TT + t) * H4 + col;
#pragma unroll
            for (int g = 0; g < 4; g++)
                xzv[g][r] = __ldg(xz + base + g * HH);
        }

        unsigned long long acc[4][2];   // [gate][row-pair]
#pragma unroll
        for (int g = 0; g < 4; g++) { acc[g][0] = 0ull; acc[g][1] = 0ull; }

        // prefetch h chunk 0 (L2-coherent; L1 not coherent across SMs)
        float4 pre[8];
        const float* hrow = hprev + srow * HH + skh;
#pragma unroll
        for (int j = 0; j < 8; j++)
            pre[j] = __ldcg((const float4*)(hrow + j * 4));

        for (int kc = 0; kc < NCHUNK; kc++) {
            __syncthreads();   // previous chunk fully consumed
#pragma unroll
            for (int j = 0; j < 8; j++) {
                const int kk = skh + j * 4;
                hs[(kk + 0) * 64 + srow] = pre[j].x;
                hs[(kk + 1) * 64 + srow] = pre[j].y;
                hs[(kk + 2) * 64 + srow] = pre[j].z;
                hs[(kk + 3) * 64 + srow] = pre[j].w;
            }
            if (kc < NCHUNK - 1) {
                const float* hn2 = hprev + srow * HH + (kc + 1) * KC + skh;
#pragma unroll
                for (int j = 0; j < 8; j++)
                    pre[j] = __ldcg((const float4*)(hn2 + j * 4));
            }
            __syncthreads();   // hs ready

            const float* usb = us + (kc * KC) * 32 + cg * 4;
#pragma unroll 8
            for (int kk = 0; kk < KC; kk++) {
                const float4 u4 = *(const float4*)(usb + kk * 32);
                const float4 h4 = *(const float4*)&hs[kk * 64 + rg4];
                const unsigned long long h01 = pack2(h4.x, h4.y);
                const unsigned long long h23 = pack2(h4.z, h4.w);
                const unsigned long long ui = splat2(u4.x);
                const unsigned long long uf = splat2(u4.y);
                const unsigned long long ug = splat2(u4.z);
                const unsigned long long uo = splat2(u4.w);
                ffma2(acc[0][0], h01, ui); ffma2(acc[0][1], h23, ui);
                ffma2(acc[1][0], h01, uf); ffma2(acc[1][1], h23, uf);
                ffma2(acc[2][0], h01, ug); ffma2(acc[2][1], h23, ug);
                ffma2(acc[3][0], h01, uo); ffma2(acc[3][1], h23, uo);
            }
        }

        // epilogue: gates + masked state update
        float z[4][4];
#pragma unroll
        for (int g = 0; g < 4; g++) {
            unpack2(acc[g][0], z[g][0], z[g][1]);
            unpack2(acc[g][1], z[g][2], z[g][3]);
        }
#pragma unroll
        for (int r = 0; r < 4; r++) {
            const int row = rg4 + r;
            const float zi = z[0][r] + xzv[0][r];
            const float zf = z[1][r] + xzv[1][r];
            const float zg = z[2][r] + xzv[2][r];
            const float zo = z[3][r] + xzv[3][r];
            const float ig = 1.f / (1.f + __expf(-zi));
            const float fg = 1.f / (1.f + __expf(-zf));
            const float gg = tanhf(zg);
            const float og = 1.f / (1.f + __expf(-zo));
            const float cn = fg * creg[r] + ig * gg;
            const float hn = og * tanhf(cn);
            const bool m = t < lenr[r];
            creg[r] = m ? cn : creg[r];
            hreg[r] = m ? hn : hreg[r];
            hnext[row * HH + col] = hreg[r];
            out[((size_t)row * TT + t) * HH + col] = hreg[r];
        }
        grid_barrier();
    }

    if (finalHC) {
#pragma unroll
        for (int r = 0; r < 4; r++) {
            const int idx = (rg4 + r) * HH + col;
            finalHC[idx]            = hreg[r];
            finalHC[BSZ * HH + idx] = creg[r];
        }
    }
}

// ---------------------------------------------------------------------------
extern "C" void kernel_launch(void* const* d_in, const int* in_sizes, int n_in,
                              void* d_out, int out_size)
{
    const float* x   = (const float*)d_in[0];   // (B,T,D)
    const int*   len = (const int*)  d_in[1];   // (B,)
    const float* W0  = (const float*)d_in[2];   // (D,4H)
    const float* U0  = (const float*)d_in[3];   // (H,4H)
    const float* b0  = (const float*)d_in[4];   // (4H,)
    const float* W1  = (const float*)d_in[5];   // (H,4H)
    const float* U1  = (const float*)d_in[6];   // (H,4H)
    const float* b1  = (const float*)d_in[7];   // (4H,)
    float* outf = (float*)d_out;                // rnnout | h | c

    float *xz, *out0, *h0, *h1;
    cudaGetSymbolAddress((void**)&xz,   g_xz);
    cudaGetSymbolAddress((void**)&out0, g_out0);
    cudaGetSymbolAddress((void**)&h0,   g_h0);
    cudaGetSymbolAddress((void**)&h1,   g_h1);

    const int smemBytes = (HH * 32 + KC * 64) * sizeof(float);  // 147456
    cudaFuncSetAttribute(lstm_layer, cudaFuncAttributeMaxDynamicSharedMemorySize,
                         smemBytes);

    const dim3 gGemm(H4 / 128, BT / 128);  // (32, 256)

    // ---- Layer 0 ----
    sgemm_bias<<<gGemm, 256>>>(x, W0, b0, xz, DD);
    lstm_layer<<<NBLK, 128, smemBytes>>>(xz, U0, len, h0, h1, out0, nullptr);

    // ---- Layer 1 ----
    sgemm_bias<<<gGemm, 256>>>(out0, W1, b1, xz, HH);
    lstm_layer<<<NBLK, 128, smemBytes>>>(xz, U1, len, h0, h1, outf,
                                         outf + (size_t)BT * HH);
}